// round 1
// baseline (speedup 1.0000x reference)
#include <cuda_runtime.h>
#include <math.h>

#define N_NODES 200000
#define N_DEST  8192
#define N_EDGE  262144
#define D_MEM   128
#define D_FEAT  128
#define D_EDGE  64
#define D_TIME  32
#define D_READ  128
#define D_MSG   128

#define TILE_E  64

// ---------------- scratch (device globals: allocation-free) ----------------
__device__ float g_msg_sum[N_DEST * D_MSG];
__device__ float g_cnt[N_DEST];
__device__ int   g_idx64;

// ---------------- index-width probe -----------------------------------------
// node_ids is arange(8192). If delivered as int64 (little endian), the 32-bit
// words are [0,0,1,0,2,0,...] -> words[1]==0 && words[3]==0. If int32, words[1]==1.
__global__ void probe_kernel(const unsigned int* __restrict__ w) {
    g_idx64 = (w[1] == 0u && w[3] == 0u) ? 1 : 0;
}

__device__ __forceinline__ int idx_at(const void* p, long long i, int is64) {
    return is64 ? (int)((const long long*)p)[i] : ((const int*)p)[i];
}

// ---------------- shared micro-kernels --------------------------------------
// 32-deep K chunk: A is [32][strideA] transposed tile (col = row-in-tile),
// Ws is [32][128]. Each thread accumulates 8 rows x 4 cols.
__device__ __forceinline__ void mma_chunk(const float* __restrict__ Asub, int strideA,
                                          const float* __restrict__ Ws,
                                          int ty, int tx, float acc[8][4]) {
#pragma unroll
    for (int k = 0; k < 32; k++) {
        const float* arow = Asub + k * strideA + ty * 8;
        float4 a0 = *(const float4*)(arow);
        float4 a1 = *(const float4*)(arow + 4);
        float4 w  = *(const float4*)(Ws + k * 128 + tx * 4);
        float av[8] = {a0.x, a0.y, a0.z, a0.w, a1.x, a1.y, a1.z, a1.w};
#pragma unroll
        for (int i = 0; i < 8; i++) {
            acc[i][0] = fmaf(av[i], w.x, acc[i][0]);
            acc[i][1] = fmaf(av[i], w.y, acc[i][1]);
            acc[i][2] = fmaf(av[i], w.z, acc[i][2]);
            acc[i][3] = fmaf(av[i], w.w, acc[i][3]);
        }
    }
}

// Load 32x128 weight chunk (contiguous 16KB) into smem.
__device__ __forceinline__ void load_w(float* Ws, const float* __restrict__ Wsrc, int tid) {
    const float4* s = (const float4*)Wsrc;
    float4* d = (float4*)Ws;
#pragma unroll
    for (int i = 0; i < 4; i++) d[tid + i * 256] = s[tid + i * 256];
}

__device__ __forceinline__ void zero_acc(float acc[8][4]) {
#pragma unroll
    for (int i = 0; i < 8; i++)
#pragma unroll
        for (int c = 0; c < 4; c++) acc[i][c] = 0.f;
}

// ---------------- edge pipeline ----------------------------------------------
// One block = 64 edges. Phase1: src_read = relu([mem|feat] @ W_read + b).
// Phase2: msgs = relu([src_read|edge_feat|time] @ W_msg + b).
// Phase3: run-coalesced segment-sum atomics (dest_seg is globally sorted).
__device__ __forceinline__ void flush_seg(int d, int tx, float r0, float r1, float r2,
                                          float r3, float rl) {
    float* p = g_msg_sum + (size_t)d * D_MSG + tx * 4;
    atomicAdd(p + 0, r0);
    atomicAdd(p + 1, r1);
    atomicAdd(p + 2, r2);
    atomicAdd(p + 3, r3);
    if (tx == 0) atomicAdd(&g_cnt[d], rl);
}

__global__ __launch_bounds__(256) void edge_kernel(
    const float* __restrict__ node_memory, const float* __restrict__ node_features,
    const float* __restrict__ edge_features, const float* __restrict__ time_encoding,
    const void* __restrict__ source_ids, const void* __restrict__ edge_ids,
    const void* __restrict__ dest_seg,
    const float* __restrict__ W_read, const float* __restrict__ b_read,
    const float* __restrict__ W_msg, const float* __restrict__ b_msg) {
    extern __shared__ float sm[];
    float* As  = sm;           // [32][64]   2048 floats
    float* Ws  = sm + 2048;    // [32][128]  4096 floats
    float* A2T = sm + 6144;    // [224][68]  15232 floats (padded stride 68)
    __shared__ int s_src[TILE_E], s_eid[TILE_E], s_dst[TILE_E];

    const int tid = threadIdx.x;
    const int tx = tid & 31;   // col group (4 cols)
    const int ty = tid >> 5;   // edge group (8 edges)
    const int eL = tid & 63;
    const int kq = tid >> 6;   // 0..3
    const long long ebase = (long long)blockIdx.x * TILE_E;
    const int is64 = g_idx64;

    if (tid < TILE_E) {
        s_src[tid] = idx_at(source_ids, ebase + tid, is64);
        s_eid[tid] = idx_at(edge_ids, ebase + tid, is64);
        s_dst[tid] = idx_at(dest_seg, ebase + tid, is64);
    }

    float acc[8][4];
    zero_acc(acc);

    // ---- Phase 1: src_read GEMM, K=256 in 8 chunks ----
    for (int kc = 0; kc < 8; kc++) {
        __syncthreads();
        {
            const float* row = (kc < 4)
                ? node_memory + (size_t)s_src[eL] * D_MEM + kc * 32
                : node_features + (size_t)s_src[eL] * D_FEAT + (kc - 4) * 32;
            float4 v0 = ((const float4*)row)[kq * 2];
            float4 v1 = ((const float4*)row)[kq * 2 + 1];
            int kb = kq * 8;
            As[(kb + 0) * 64 + eL] = v0.x; As[(kb + 1) * 64 + eL] = v0.y;
            As[(kb + 2) * 64 + eL] = v0.z; As[(kb + 3) * 64 + eL] = v0.w;
            As[(kb + 4) * 64 + eL] = v1.x; As[(kb + 5) * 64 + eL] = v1.y;
            As[(kb + 6) * 64 + eL] = v1.z; As[(kb + 7) * 64 + eL] = v1.w;
        }
        load_w(Ws, W_read + kc * 32 * 128, tid);
        __syncthreads();
        mma_chunk(As, 64, Ws, ty, tx, acc);
    }

    // epilogue: relu + bias, write transposed into A2T rows [0,128)
    {
        float4 bb = *(const float4*)&b_read[tx * 4];
        __syncthreads();
#pragma unroll
        for (int i = 0; i < 8; i++) {
            int e = ty * 8 + i;
            A2T[(tx * 4 + 0) * 68 + e] = fmaxf(acc[i][0] + bb.x, 0.f);
            A2T[(tx * 4 + 1) * 68 + e] = fmaxf(acc[i][1] + bb.y, 0.f);
            A2T[(tx * 4 + 2) * 68 + e] = fmaxf(acc[i][2] + bb.z, 0.f);
            A2T[(tx * 4 + 3) * 68 + e] = fmaxf(acc[i][3] + bb.w, 0.f);
        }
    }

    // fill A2T rows [128,192) = edge_features, [192,224) = time_encoding
    {
        const float4* ef = (const float4*)(edge_features + (size_t)s_eid[eL] * D_EDGE) + kq * 4;
#pragma unroll
        for (int j = 0; j < 4; j++) {
            float4 v = ef[j];
            int kk = 128 + kq * 16 + j * 4;
            A2T[(kk + 0) * 68 + eL] = v.x; A2T[(kk + 1) * 68 + eL] = v.y;
            A2T[(kk + 2) * 68 + eL] = v.z; A2T[(kk + 3) * 68 + eL] = v.w;
        }
        if (kq < 2) {
            const float4* tf = (const float4*)(time_encoding + (ebase + eL) * D_TIME) + kq * 4;
#pragma unroll
            for (int j = 0; j < 4; j++) {
                float4 v = tf[j];
                int kk = 192 + kq * 16 + j * 4;
                A2T[(kk + 0) * 68 + eL] = v.x; A2T[(kk + 1) * 68 + eL] = v.y;
                A2T[(kk + 2) * 68 + eL] = v.z; A2T[(kk + 3) * 68 + eL] = v.w;
            }
        }
    }

    // ---- Phase 2: msg GEMM, K=224 in 7 chunks ----
    zero_acc(acc);
    for (int kc = 0; kc < 7; kc++) {
        __syncthreads();
        load_w(Ws, W_msg + kc * 32 * 128, tid);
        __syncthreads();
        mma_chunk(A2T + kc * 32 * 68, 68, Ws, ty, tx, acc);
    }

    // ---- Phase 3: bias+relu, run-coalesced segment atomics ----
    {
        float4 bm = *(const float4*)&b_msg[tx * 4];
        int curd = s_dst[ty * 8];
        float r0 = 0.f, r1 = 0.f, r2 = 0.f, r3 = 0.f, rl = 0.f;
#pragma unroll
        for (int i = 0; i < 8; i++) {
            int d = s_dst[ty * 8 + i];
            float m0 = fmaxf(acc[i][0] + bm.x, 0.f);
            float m1 = fmaxf(acc[i][1] + bm.y, 0.f);
            float m2 = fmaxf(acc[i][2] + bm.z, 0.f);
            float m3 = fmaxf(acc[i][3] + bm.w, 0.f);
            if (d != curd) {
                flush_seg(curd, tx, r0, r1, r2, r3, rl);
                curd = d; r0 = r1 = r2 = r3 = rl = 0.f;
            }
            r0 += m0; r1 += m1; r2 += m2; r3 += m3; rl += 1.f;
        }
        flush_seg(curd, tx, r0, r1, r2, r3, rl);
    }
}

// ---------------- dest pipeline ----------------------------------------------
// One block = 64 dest rows. dst_read -> agg -> upd -> write(tanh) -> scatter.
__global__ __launch_bounds__(256) void dest_kernel(
    const float* __restrict__ node_memory, const float* __restrict__ node_features,
    const void* __restrict__ node_ids,
    const float* __restrict__ W_read, const float* __restrict__ b_read,
    const float* __restrict__ W_agg, const float* __restrict__ b_agg,
    const float* __restrict__ W_upd, const float* __restrict__ b_upd,
    const float* __restrict__ W_write, const float* __restrict__ b_write,
    float* __restrict__ out) {
    extern __shared__ float sm[];
    float* As = sm;             // [32][64]
    float* Ws = sm + 2048;      // [32][128]
    float* CT = sm + 6144;      // [256][68]  17408 floats
    float* DR = sm + 23552;     // [128][68]  8704 floats
    __shared__ int s_nid[TILE_E];

    const int tid = threadIdx.x;
    const int tx = tid & 31;
    const int ty = tid >> 5;
    const int eL = tid & 63;
    const int kq = tid >> 6;
    const int rbase = blockIdx.x * TILE_E;
    const int is64 = g_idx64;

    if (tid < TILE_E) s_nid[tid] = idx_at(node_ids, rbase + tid, is64);

    float acc[8][4];
    zero_acc(acc);

    // ---- P1: dst_read GEMM (K=256) ----
    for (int kc = 0; kc < 8; kc++) {
        __syncthreads();
        {
            const float* row = (kc < 4)
                ? node_memory + (size_t)s_nid[eL] * D_MEM + kc * 32
                : node_features + (size_t)s_nid[eL] * D_FEAT + (kc - 4) * 32;
            float4 v0 = ((const float4*)row)[kq * 2];
            float4 v1 = ((const float4*)row)[kq * 2 + 1];
            int kb = kq * 8;
            As[(kb + 0) * 64 + eL] = v0.x; As[(kb + 1) * 64 + eL] = v0.y;
            As[(kb + 2) * 64 + eL] = v0.z; As[(kb + 3) * 64 + eL] = v0.w;
            As[(kb + 4) * 64 + eL] = v1.x; As[(kb + 5) * 64 + eL] = v1.y;
            As[(kb + 6) * 64 + eL] = v1.z; As[(kb + 7) * 64 + eL] = v1.w;
        }
        load_w(Ws, W_read + kc * 32 * 128, tid);
        __syncthreads();
        mma_chunk(As, 64, Ws, ty, tx, acc);
    }
    // epilogue -> CT rows [0,128) and DR
    {
        float4 bb = *(const float4*)&b_read[tx * 4];
        __syncthreads();
#pragma unroll
        for (int i = 0; i < 8; i++) {
            int e = ty * 8 + i;
#pragma unroll
            for (int c = 0; c < 4; c++) {
                float bv = (c == 0) ? bb.x : (c == 1) ? bb.y : (c == 2) ? bb.z : bb.w;
                float v = fmaxf(acc[i][c] + bv, 0.f);
                CT[(tx * 4 + c) * 68 + e] = v;
                DR[(tx * 4 + c) * 68 + e] = v;
            }
        }
    }
    // CT rows [128,256) = msg_mean
    {
        int dg = rbase + eL;
        float inv = 1.0f / fmaxf(g_cnt[dg], 1.0f);
        const float4* srcp = (const float4*)(g_msg_sum + (size_t)dg * D_MSG + kq * 32);
#pragma unroll
        for (int j4 = 0; j4 < 8; j4++) {
            float4 v = srcp[j4];
            int kk = 128 + kq * 32 + j4 * 4;
            CT[(kk + 0) * 68 + eL] = v.x * inv; CT[(kk + 1) * 68 + eL] = v.y * inv;
            CT[(kk + 2) * 68 + eL] = v.z * inv; CT[(kk + 3) * 68 + eL] = v.w * inv;
        }
    }

    // ---- P2: agg GEMM (K=256) over CT ----
    zero_acc(acc);
    for (int kc = 0; kc < 8; kc++) {
        __syncthreads();
        load_w(Ws, W_agg + kc * 32 * 128, tid);
        __syncthreads();
        mma_chunk(CT + kc * 32 * 68, 68, Ws, ty, tx, acc);
    }
    __syncthreads();
    {
        float4 ba = *(const float4*)&b_agg[tx * 4];
#pragma unroll
        for (int i = 0; i < 8; i++) {
            int e = ty * 8 + i;
            CT[(tx * 4 + 0) * 68 + e] = fmaxf(acc[i][0] + ba.x, 0.f);
            CT[(tx * 4 + 1) * 68 + e] = fmaxf(acc[i][1] + ba.y, 0.f);
            CT[(tx * 4 + 2) * 68 + e] = fmaxf(acc[i][2] + ba.z, 0.f);
            CT[(tx * 4 + 3) * 68 + e] = fmaxf(acc[i][3] + ba.w, 0.f);
        }
        // CT rows [128,256) = dst_read (copy from DR)
#pragma unroll
        for (int j = 0; j < 32; j++) {
            int row = kq * 32 + j;
            CT[(128 + row) * 68 + eL] = DR[row * 68 + eL];
        }
    }

    // ---- P3: upd GEMM (K=256) over CT ----
    zero_acc(acc);
    for (int kc = 0; kc < 8; kc++) {
        __syncthreads();
        load_w(Ws, W_upd + kc * 32 * 128, tid);
        __syncthreads();
        mma_chunk(CT + kc * 32 * 68, 68, Ws, ty, tx, acc);
    }
    __syncthreads();
    {
        float4 bu = *(const float4*)&b_upd[tx * 4];
#pragma unroll
        for (int i = 0; i < 8; i++) {
            int e = ty * 8 + i;
            DR[(tx * 4 + 0) * 68 + e] = fmaxf(acc[i][0] + bu.x, 0.f);
            DR[(tx * 4 + 1) * 68 + e] = fmaxf(acc[i][1] + bu.y, 0.f);
            DR[(tx * 4 + 2) * 68 + e] = fmaxf(acc[i][2] + bu.z, 0.f);
            DR[(tx * 4 + 3) * 68 + e] = fmaxf(acc[i][3] + bu.w, 0.f);
        }
    }

    // ---- P4: write GEMM (K=128) over DR, tanh, scatter ----
    zero_acc(acc);
    for (int kc = 0; kc < 4; kc++) {
        __syncthreads();
        load_w(Ws, W_write + kc * 32 * 128, tid);
        __syncthreads();
        mma_chunk(DR + kc * 32 * 68, 68, Ws, ty, tx, acc);
    }
    {
        float4 bw = *(const float4*)&b_write[tx * 4];
#pragma unroll
        for (int i = 0; i < 8; i++) {
            int e = ty * 8 + i;
            float4 o;
            o.x = tanhf(acc[i][0] + bw.x);
            o.y = tanhf(acc[i][1] + bw.y);
            o.z = tanhf(acc[i][2] + bw.z);
            o.w = tanhf(acc[i][3] + bw.w);
            *(float4*)(out + (size_t)s_nid[e] * D_MEM + tx * 4) = o;
        }
    }
}

// ---------------- launch ------------------------------------------------------
#define EDGE_SMEM ((2048 + 4096 + 224 * 68) * 4)
#define DEST_SMEM ((2048 + 4096 + 256 * 68 + 128 * 68) * 4)

extern "C" void kernel_launch(void* const* d_in, const int* in_sizes, int n_in,
                              void* d_out, int out_size) {
    const float* node_memory   = (const float*)d_in[0];
    const float* node_features = (const float*)d_in[1];
    const float* edge_features = (const float*)d_in[2];
    const float* time_encoding = (const float*)d_in[3];
    const void*  node_ids      = d_in[4];
    const void*  source_ids    = d_in[5];
    const void*  edge_ids      = d_in[6];
    const void*  dest_seg      = d_in[7];
    const float* W_read  = (const float*)d_in[8];
    const float* b_read  = (const float*)d_in[9];
    const float* W_msg   = (const float*)d_in[10];
    const float* b_msg   = (const float*)d_in[11];
    const float* W_agg   = (const float*)d_in[12];
    const float* b_agg   = (const float*)d_in[13];
    const float* W_upd   = (const float*)d_in[14];
    const float* b_upd   = (const float*)d_in[15];
    const float* W_write = (const float*)d_in[16];
    const float* b_write = (const float*)d_in[17];
    float* out = (float*)d_out;

    cudaFuncSetAttribute(edge_kernel, cudaFuncAttributeMaxDynamicSharedMemorySize, EDGE_SMEM);
    cudaFuncSetAttribute(dest_kernel, cudaFuncAttributeMaxDynamicSharedMemorySize, DEST_SMEM);

    void* sumP = nullptr;
    void* cntP = nullptr;
    cudaGetSymbolAddress(&sumP, g_msg_sum);
    cudaGetSymbolAddress(&cntP, g_cnt);

    probe_kernel<<<1, 1>>>((const unsigned int*)node_ids);
    cudaMemsetAsync(sumP, 0, sizeof(float) * N_DEST * D_MSG);
    cudaMemsetAsync(cntP, 0, sizeof(float) * N_DEST);
    cudaMemcpyAsync(d_out, d_in[0], (size_t)N_NODES * D_MEM * sizeof(float),
                    cudaMemcpyDeviceToDevice);

    edge_kernel<<<N_EDGE / TILE_E, 256, EDGE_SMEM>>>(
        node_memory, node_features, edge_features, time_encoding,
        source_ids, edge_ids, dest_seg, W_read, b_read, W_msg, b_msg);

    dest_kernel<<<N_DEST / TILE_E, 256, DEST_SMEM>>>(
        node_memory, node_features, node_ids,
        W_read, b_read, W_agg, b_agg, W_upd, b_upd, W_write, b_write, out);
}